// round 1
// baseline (speedup 1.0000x reference)
#include <cuda_runtime.h>
#include <math.h>

// Problem constants
#define Bb   128
#define Cc   1024
#define Hh   24
#define Ww   12
#define Nn   288           // H*W
#define EPSv 1e-5f

// ---------------------------------------------------------------------------
// Scratch (static device globals — allocation-free per harness rules)
// ---------------------------------------------------------------------------
__device__ float g_F [(size_t)Bb * Nn * Nn];   // spatial attention (b, n, n)
__device__ float g_Y [(size_t)Bb * Cc * Nn];   // spatial AV output
__device__ float g_Z [(size_t)Bb * Cc * Nn];   // residual 1 output
__device__ float g_Y2[(size_t)Bb * Cc * Nn];   // channel AV output
__device__ float g_F2[(size_t)Bb * Cc * Cc];   // channel attention (b, c, c)
__device__ float g_scale[Cc];
__device__ float g_shift[Cc];

// ---------------------------------------------------------------------------
// Block reduction helper (works for blockDim.x in {256, 288})
// op: 0 = max, 1 = sum
// ---------------------------------------------------------------------------
__device__ __forceinline__ float block_reduce(float v, int op) {
    __shared__ float red[32];
    #pragma unroll
    for (int o = 16; o > 0; o >>= 1) {
        float other = __shfl_xor_sync(0xffffffffu, v, o);
        v = op ? (v + other) : fmaxf(v, other);
    }
    int lane = threadIdx.x & 31;
    int wid  = threadIdx.x >> 5;
    int nw   = (blockDim.x + 31) >> 5;
    if (lane == 0) red[wid] = v;
    __syncthreads();
    if (wid == 0) {
        float r = (lane < nw) ? red[lane] : (op ? 0.0f : -3.4e38f);
        #pragma unroll
        for (int o = 16; o > 0; o >>= 1) {
            float other = __shfl_xor_sync(0xffffffffu, r, o);
            r = op ? (r + other) : fmaxf(r, other);
        }
        if (lane == 0) red[0] = r;
    }
    __syncthreads();
    float r = red[0];
    __syncthreads();   // protect red[] before next call
    return r;
}

// ---------------------------------------------------------------------------
// GEMM TN (gram): C[b,m,n] = alpha * sum_k A[b,k,m] * A[b,k,n]
// A viewed as (K x Md) with row stride lda (= Nn); both tiles load coalesced.
// 64x64 tile, BK=16, 256 threads, 4x4 microtile.
// ---------------------------------------------------------------------------
__global__ __launch_bounds__(256) void k_gemm_tn(
    const float* __restrict__ A, float* __restrict__ Cd,
    int Md, int K, int lda, size_t sA, size_t sC, float alpha)
{
    __shared__ float As[16][64];
    __shared__ float Bs[16][64];
    int bz = blockIdx.z;
    int m0 = blockIdx.y * 64;
    int n0 = blockIdx.x * 64;
    const float* Ab = A + (size_t)bz * sA;

    int t  = threadIdx.x;
    int tx = t & 15, ty = t >> 4;
    int lr = t >> 4;            // load row (k within tile)
    int lc = (t & 15) * 4;      // load col (m/n within tile)

    float acc[4][4] = {};
    for (int k0 = 0; k0 < K; k0 += 16) {
        const float* ap = Ab + (size_t)(k0 + lr) * lda + m0 + lc;
        const float* bp = Ab + (size_t)(k0 + lr) * lda + n0 + lc;
        #pragma unroll
        for (int i = 0; i < 4; i++) {
            As[lr][lc + i] = (m0 + lc + i < Md) ? ap[i] : 0.0f;
            Bs[lr][lc + i] = (n0 + lc + i < Md) ? bp[i] : 0.0f;
        }
        __syncthreads();
        #pragma unroll
        for (int kk = 0; kk < 16; kk++) {
            float4 a4 = *(const float4*)&As[kk][ty * 4];
            float4 b4 = *(const float4*)&Bs[kk][tx * 4];
            float av[4] = {a4.x, a4.y, a4.z, a4.w};
            float bv[4] = {b4.x, b4.y, b4.z, b4.w};
            #pragma unroll
            for (int i = 0; i < 4; i++)
                #pragma unroll
                for (int j = 0; j < 4; j++)
                    acc[i][j] += av[i] * bv[j];
        }
        __syncthreads();
    }
    #pragma unroll
    for (int i = 0; i < 4; i++) {
        int m = m0 + ty * 4 + i;
        if (m >= Md) continue;
        #pragma unroll
        for (int j = 0; j < 4; j++) {
            int n = n0 + tx * 4 + j;
            if (n < Md)
                Cd[(size_t)bz * sC + (size_t)m * Md + n] = acc[i][j] * alpha;
        }
    }
}

// ---------------------------------------------------------------------------
// GEMM NT: C[b,m,n] = sum_k A[b,m,k] * B[b,n,k]
// Both operands row-major with K contiguous; transpose-loaded into k-major smem.
// ---------------------------------------------------------------------------
__global__ __launch_bounds__(256) void k_gemm_nt(
    const float* __restrict__ A, const float* __restrict__ Bm, float* __restrict__ Cd,
    int M, int Nd, int K, size_t sA, size_t sB, size_t sC)
{
    __shared__ float As[16][68];   // pad 68: keeps float4 row alignment, spreads banks
    __shared__ float Bs[16][68];
    int bz = blockIdx.z;
    int m0 = blockIdx.y * 64;
    int n0 = blockIdx.x * 64;
    const float* Ab  = A  + (size_t)bz * sA;
    const float* Bmb = Bm + (size_t)bz * sB;

    int t  = threadIdx.x;
    int tx = t & 15, ty = t >> 4;
    int mr = t >> 2;            // row within tile (0..63)
    int kc = (t & 3) * 4;       // k offset within tile (0,4,8,12)

    float acc[4][4] = {};
    for (int k0 = 0; k0 < K; k0 += 16) {
        int gm = m0 + mr;
        int gn = n0 + mr;
        const float* ap = Ab  + (size_t)gm * K + k0 + kc;
        const float* bp = Bmb + (size_t)gn * K + k0 + kc;
        #pragma unroll
        for (int i = 0; i < 4; i++) {
            As[kc + i][mr] = (gm < M)  ? ap[i] : 0.0f;
            Bs[kc + i][mr] = (gn < Nd) ? bp[i] : 0.0f;
        }
        __syncthreads();
        #pragma unroll
        for (int kk = 0; kk < 16; kk++) {
            float4 a4 = *(const float4*)&As[kk][ty * 4];
            float4 b4 = *(const float4*)&Bs[kk][tx * 4];
            float av[4] = {a4.x, a4.y, a4.z, a4.w};
            float bv[4] = {b4.x, b4.y, b4.z, b4.w};
            #pragma unroll
            for (int i = 0; i < 4; i++)
                #pragma unroll
                for (int j = 0; j < 4; j++)
                    acc[i][j] += av[i] * bv[j];
        }
        __syncthreads();
    }
    #pragma unroll
    for (int i = 0; i < 4; i++) {
        int m = m0 + ty * 4 + i;
        if (m >= M) continue;
        #pragma unroll
        for (int j = 0; j < 4; j++) {
            int n = n0 + tx * 4 + j;
            if (n < Nd)
                Cd[(size_t)bz * sC + (size_t)m * Nd + n] = acc[i][j];
        }
    }
}

// ---------------------------------------------------------------------------
// GEMM NN: C[b,m,n] = sum_k A[b,m,k] * B[b,k,n]
// A transpose-loaded; B loaded directly (k-major rows already).
// ---------------------------------------------------------------------------
__global__ __launch_bounds__(256) void k_gemm_nn(
    const float* __restrict__ A, const float* __restrict__ Bm, float* __restrict__ Cd,
    int M, int Nd, int K, size_t sA, size_t sB, size_t sC)
{
    __shared__ float As[16][68];
    __shared__ float Bs[16][68];
    int bz = blockIdx.z;
    int m0 = blockIdx.y * 64;
    int n0 = blockIdx.x * 64;
    const float* Ab  = A  + (size_t)bz * sA;
    const float* Bmb = Bm + (size_t)bz * sB;

    int t  = threadIdx.x;
    int tx = t & 15, ty = t >> 4;
    int amr = t >> 2, akc = (t & 3) * 4;    // A transpose-load
    int bkr = t >> 4, bnc = (t & 15) * 4;   // B direct load

    float acc[4][4] = {};
    for (int k0 = 0; k0 < K; k0 += 16) {
        int gm = m0 + amr;
        const float* ap = Ab + (size_t)gm * K + k0 + akc;
        #pragma unroll
        for (int i = 0; i < 4; i++)
            As[akc + i][amr] = (gm < M) ? ap[i] : 0.0f;
        const float* bp = Bmb + (size_t)(k0 + bkr) * Nd + n0 + bnc;
        #pragma unroll
        for (int i = 0; i < 4; i++)
            Bs[bkr][bnc + i] = (n0 + bnc + i < Nd) ? bp[i] : 0.0f;
        __syncthreads();
        #pragma unroll
        for (int kk = 0; kk < 16; kk++) {
            float4 a4 = *(const float4*)&As[kk][ty * 4];
            float4 b4 = *(const float4*)&Bs[kk][tx * 4];
            float av[4] = {a4.x, a4.y, a4.z, a4.w};
            float bv[4] = {b4.x, b4.y, b4.z, b4.w};
            #pragma unroll
            for (int i = 0; i < 4; i++)
                #pragma unroll
                for (int j = 0; j < 4; j++)
                    acc[i][j] += av[i] * bv[j];
        }
        __syncthreads();
    }
    #pragma unroll
    for (int i = 0; i < 4; i++) {
        int m = m0 + ty * 4 + i;
        if (m >= M) continue;
        #pragma unroll
        for (int j = 0; j < 4; j++) {
            int n = n0 + tx * 4 + j;
            if (n < Nd)
                Cd[(size_t)bz * sC + (size_t)m * Nd + n] = acc[i][j];
        }
    }
}

// ---------------------------------------------------------------------------
// Spatial softmax with gaussian prior: per row (b,p) of g_F (length Nn=288):
//   p1 = softmax(row); w = p1 * dis[p,:]; row = softmax(w)
// One block (288 threads) per row. grid = (Nn, Bb)
// ---------------------------------------------------------------------------
__global__ __launch_bounds__(288) void k_softmax_prior(const float* __restrict__ dis)
{
    int p = blockIdx.x;
    int b = blockIdx.y;
    float* f = g_F + ((size_t)b * Nn + p) * Nn;
    const float* d = dis + (size_t)p * Nn;
    int t = threadIdx.x;

    float v = f[t];
    float m1 = block_reduce(v, 0);
    float e1 = __expf(v - m1);
    float s1 = block_reduce(e1, 1);
    float w  = (e1 / s1) * d[t];
    float m2 = block_reduce(w, 0);
    float e2 = __expf(w - m2);
    float s2 = block_reduce(e2, 1);
    f[t] = e2 / s2;
}

// ---------------------------------------------------------------------------
// Channel softmax: rows of g_F2 (length Cc=1024), 256 threads x 4 elems.
// grid = Bb*Cc (1D)
// ---------------------------------------------------------------------------
__global__ __launch_bounds__(256) void k_softmax_chan()
{
    size_t row = blockIdx.x;
    float* f = g_F2 + row * (size_t)Cc;
    int t = threadIdx.x;

    float v[4];
    #pragma unroll
    for (int i = 0; i < 4; i++) v[i] = f[t + 256 * i];
    float lm = fmaxf(fmaxf(v[0], v[1]), fmaxf(v[2], v[3]));
    float m = block_reduce(lm, 0);
    float e[4], ls = 0.0f;
    #pragma unroll
    for (int i = 0; i < 4; i++) { e[i] = __expf(v[i] - m); ls += e[i]; }
    float s = block_reduce(ls, 1);
    float inv = 1.0f / s;
    #pragma unroll
    for (int i = 0; i < 4; i++) f[t + 256 * i] = e[i] * inv;
}

// ---------------------------------------------------------------------------
// BatchNorm stats: per channel mean/var over (B, N). Writes fused scale/shift.
// One block (256 thr) per channel.
// ---------------------------------------------------------------------------
__global__ __launch_bounds__(256) void k_bnstats(
    const float* __restrict__ Y,
    const float* __restrict__ gamma, const float* __restrict__ beta)
{
    int c = blockIdx.x;
    int t = threadIdx.x;
    float s = 0.0f, sq = 0.0f;
    for (int b = 0; b < Bb; b++) {
        const float* y = Y + ((size_t)b * Cc + c) * Nn;
        for (int i = t; i < Nn; i += 256) {
            float v = y[i];
            s  += v;
            sq += v * v;
        }
    }
    s  = block_reduce(s, 1);
    sq = block_reduce(sq, 1);
    if (t == 0) {
        const float invN = 1.0f / (float)(Bb * Nn);
        float mean = s * invN;
        float var  = sq * invN - mean * mean;
        float sc = gamma[c] * rsqrtf(var + EPSv);
        g_scale[c] = sc;
        g_shift[c] = beta[c] - mean * sc;
    }
}

// ---------------------------------------------------------------------------
// out = scale[c]*y + shift[c] + residual   (vectorized float4; Nn % 4 == 0)
// ---------------------------------------------------------------------------
__global__ __launch_bounds__(256) void k_bn_apply_add(
    const float* __restrict__ Y, const float* __restrict__ R, float* __restrict__ out)
{
    size_t i4 = (size_t)blockIdx.x * blockDim.x + threadIdx.x;
    const size_t total4 = (size_t)Bb * Cc * Nn / 4;
    if (i4 >= total4) return;
    size_t e = i4 * 4;
    int c = (int)((e / Nn) % Cc);
    float4 y = ((const float4*)Y)[i4];
    float4 r = ((const float4*)R)[i4];
    float sc = g_scale[c], sh = g_shift[c];
    float4 o;
    o.x = fmaf(sc, y.x, sh) + r.x;
    o.y = fmaf(sc, y.y, sh) + r.y;
    o.z = fmaf(sc, y.z, sh) + r.z;
    o.w = fmaf(sc, y.w, sh) + r.w;
    ((float4*)out)[i4] = o;
}

// ---------------------------------------------------------------------------
// Launch
// ---------------------------------------------------------------------------
extern "C" void kernel_launch(void* const* d_in, const int* in_sizes, int n_in,
                              void* d_out, int out_size)
{
    const float* x      = (const float*)d_in[0];
    const float* dis    = (const float*)d_in[1];
    const float* gamma1 = (const float*)d_in[2];
    const float* beta1  = (const float*)d_in[3];
    const float* gamma2 = (const float*)d_in[4];
    const float* beta2  = (const float*)d_in[5];
    float* out = (float*)d_out;

    float *pF, *pY, *pZ, *pY2, *pF2;
    cudaGetSymbolAddress((void**)&pF,  g_F);
    cudaGetSymbolAddress((void**)&pY,  g_Y);
    cudaGetSymbolAddress((void**)&pZ,  g_Z);
    cudaGetSymbolAddress((void**)&pY2, g_Y2);
    cudaGetSymbolAddress((void**)&pF2, g_F2);

    const size_t sXN = (size_t)Cc * Nn;   // per-batch stride of (C,N) tensors
    const size_t sFF = (size_t)Nn * Nn;   // per-batch stride of F
    const size_t sCC = (size_t)Cc * Cc;   // per-batch stride of F2

    // 1) F = X^T X / sqrt(C)          (288x288, K=1024)
    k_gemm_tn<<<dim3(5, 5, Bb), 256>>>(x, pF, Nn, Cc, Nn, sXN, sFF, 0.03125f);

    // 2) softmax -> *dis -> softmax   (in place on g_F)
    k_softmax_prior<<<dim3(Nn, Bb), 288>>>(dis);

    // 3) Y = X F^T                    (1024x288, K=288)
    k_gemm_nt<<<dim3(5, 16, Bb), 256>>>(x, pF, pY, Cc, Nn, Nn, sXN, sFF, sXN);

    // 4) BN1 stats + 5) Z = bn1(Y) + X
    k_bnstats<<<Cc, 256>>>(pY, gamma1, beta1);
    {
        size_t total4 = (size_t)Bb * Cc * Nn / 4;
        int blocks = (int)((total4 + 255) / 256);
        k_bn_apply_add<<<blocks, 256>>>(pY, x, pZ);
    }

    // 6) F2 = Z Z^T                   (1024x1024, K=288)
    k_gemm_nt<<<dim3(16, 16, Bb), 256>>>(pZ, pZ, pF2, Cc, Cc, Nn, sXN, sXN, sCC);

    // 7) softmax rows of F2
    k_softmax_chan<<<Bb * Cc, 256>>>();

    // 8) Y2 = F2 Z                    (1024x288, K=1024)
    k_gemm_nn<<<dim3(5, 16, Bb), 256>>>(pF2, pZ, pY2, Cc, Nn, Cc, sCC, sXN, sXN);

    // 9) BN2 stats + 10) out = bn2(Y2) + Z
    k_bnstats<<<Cc, 256>>>(pY2, gamma2, beta2);
    {
        size_t total4 = (size_t)Bb * Cc * Nn / 4;
        int blocks = (int)((total4 + 255) / 256);
        k_bn_apply_add<<<blocks, 256>>>(pY2, pZ, out);
    }
}

// round 2
// speedup vs baseline: 1.0015x; 1.0015x over previous
#include <cuda_runtime.h>
#include <math.h>

// Problem constants
#define Bb   128
#define Cc   1024
#define Hh   24
#define Ww   12
#define Nn   288           // H*W
#define EPSv 1e-5f

// ---------------------------------------------------------------------------
// Scratch (static device globals — allocation-free per harness rules)
// ---------------------------------------------------------------------------
__device__ float g_F [(size_t)Bb * Nn * Nn];   // spatial attention (b, n, n)
__device__ float g_Y [(size_t)Bb * Cc * Nn];   // spatial AV output
__device__ float g_Z [(size_t)Bb * Cc * Nn];   // residual 1 output
__device__ float g_Y2[(size_t)Bb * Cc * Nn];   // channel AV output
__device__ float g_F2[(size_t)Bb * Cc * Cc];   // channel attention (b, c, c)
__device__ float g_scale[Cc];
__device__ float g_shift[Cc];

// ---------------------------------------------------------------------------
// Block reduction helper (works for blockDim.x in {256, 288})
// op: 0 = max, 1 = sum
// ---------------------------------------------------------------------------
__device__ __forceinline__ float block_reduce(float v, int op) {
    __shared__ float red[32];
    #pragma unroll
    for (int o = 16; o > 0; o >>= 1) {
        float other = __shfl_xor_sync(0xffffffffu, v, o);
        v = op ? (v + other) : fmaxf(v, other);
    }
    int lane = threadIdx.x & 31;
    int wid  = threadIdx.x >> 5;
    int nw   = (blockDim.x + 31) >> 5;
    if (lane == 0) red[wid] = v;
    __syncthreads();
    if (wid == 0) {
        float r = (lane < nw) ? red[lane] : (op ? 0.0f : -3.4e38f);
        #pragma unroll
        for (int o = 16; o > 0; o >>= 1) {
            float other = __shfl_xor_sync(0xffffffffu, r, o);
            r = op ? (r + other) : fmaxf(r, other);
        }
        if (lane == 0) red[0] = r;
    }
    __syncthreads();
    float r = red[0];
    __syncthreads();   // protect red[] before next call
    return r;
}

// ---------------------------------------------------------------------------
// GEMM TN (gram): C[b,m,n] = alpha * sum_k A[b,k,m] * A[b,k,n]
// A viewed as (K x Md) with row stride lda (= Nn); both tiles load coalesced.
// 64x64 tile, BK=16, 256 threads, 4x4 microtile.
// ---------------------------------------------------------------------------
__global__ __launch_bounds__(256) void k_gemm_tn(
    const float* __restrict__ A, float* __restrict__ Cd,
    int Md, int K, int lda, size_t sA, size_t sC, float alpha)
{
    __shared__ float As[16][64];
    __shared__ float Bs[16][64];
    int bz = blockIdx.z;
    int m0 = blockIdx.y * 64;
    int n0 = blockIdx.x * 64;
    const float* Ab = A + (size_t)bz * sA;

    int t  = threadIdx.x;
    int tx = t & 15, ty = t >> 4;
    int lr = t >> 4;            // load row (k within tile)
    int lc = (t & 15) * 4;      // load col (m/n within tile)

    float acc[4][4] = {};
    for (int k0 = 0; k0 < K; k0 += 16) {
        const float* ap = Ab + (size_t)(k0 + lr) * lda + m0 + lc;
        const float* bp = Ab + (size_t)(k0 + lr) * lda + n0 + lc;
        #pragma unroll
        for (int i = 0; i < 4; i++) {
            As[lr][lc + i] = (m0 + lc + i < Md) ? ap[i] : 0.0f;
            Bs[lr][lc + i] = (n0 + lc + i < Md) ? bp[i] : 0.0f;
        }
        __syncthreads();
        #pragma unroll
        for (int kk = 0; kk < 16; kk++) {
            float4 a4 = *(const float4*)&As[kk][ty * 4];
            float4 b4 = *(const float4*)&Bs[kk][tx * 4];
            float av[4] = {a4.x, a4.y, a4.z, a4.w};
            float bv[4] = {b4.x, b4.y, b4.z, b4.w};
            #pragma unroll
            for (int i = 0; i < 4; i++)
                #pragma unroll
                for (int j = 0; j < 4; j++)
                    acc[i][j] += av[i] * bv[j];
        }
        __syncthreads();
    }
    #pragma unroll
    for (int i = 0; i < 4; i++) {
        int m = m0 + ty * 4 + i;
        if (m >= Md) continue;
        #pragma unroll
        for (int j = 0; j < 4; j++) {
            int n = n0 + tx * 4 + j;
            if (n < Md)
                Cd[(size_t)bz * sC + (size_t)m * Md + n] = acc[i][j] * alpha;
        }
    }
}

// ---------------------------------------------------------------------------
// GEMM NT: C[b,m,n] = sum_k A[b,m,k] * B[b,n,k]
// Both operands row-major with K contiguous; transpose-loaded into k-major smem.
// ---------------------------------------------------------------------------
__global__ __launch_bounds__(256) void k_gemm_nt(
    const float* __restrict__ A, const float* __restrict__ Bm, float* __restrict__ Cd,
    int M, int Nd, int K, size_t sA, size_t sB, size_t sC)
{
    __shared__ float As[16][68];   // pad 68: keeps float4 row alignment, spreads banks
    __shared__ float Bs[16][68];
    int bz = blockIdx.z;
    int m0 = blockIdx.y * 64;
    int n0 = blockIdx.x * 64;
    const float* Ab  = A  + (size_t)bz * sA;
    const float* Bmb = Bm + (size_t)bz * sB;

    int t  = threadIdx.x;
    int tx = t & 15, ty = t >> 4;
    int mr = t >> 2;            // row within tile (0..63)
    int kc = (t & 3) * 4;       // k offset within tile (0,4,8,12)

    float acc[4][4] = {};
    for (int k0 = 0; k0 < K; k0 += 16) {
        int gm = m0 + mr;
        int gn = n0 + mr;
        const float* ap = Ab  + (size_t)gm * K + k0 + kc;
        const float* bp = Bmb + (size_t)gn * K + k0 + kc;
        #pragma unroll
        for (int i = 0; i < 4; i++) {
            As[kc + i][mr] = (gm < M)  ? ap[i] : 0.0f;
            Bs[kc + i][mr] = (gn < Nd) ? bp[i] : 0.0f;
        }
        __syncthreads();
        #pragma unroll
        for (int kk = 0; kk < 16; kk++) {
            float4 a4 = *(const float4*)&As[kk][ty * 4];
            float4 b4 = *(const float4*)&Bs[kk][tx * 4];
            float av[4] = {a4.x, a4.y, a4.z, a4.w};
            float bv[4] = {b4.x, b4.y, b4.z, b4.w};
            #pragma unroll
            for (int i = 0; i < 4; i++)
                #pragma unroll
                for (int j = 0; j < 4; j++)
                    acc[i][j] += av[i] * bv[j];
        }
        __syncthreads();
    }
    #pragma unroll
    for (int i = 0; i < 4; i++) {
        int m = m0 + ty * 4 + i;
        if (m >= M) continue;
        #pragma unroll
        for (int j = 0; j < 4; j++) {
            int n = n0 + tx * 4 + j;
            if (n < Nd)
                Cd[(size_t)bz * sC + (size_t)m * Nd + n] = acc[i][j];
        }
    }
}

// ---------------------------------------------------------------------------
// GEMM NN: C[b,m,n] = sum_k A[b,m,k] * B[b,k,n]
// A transpose-loaded; B loaded directly (k-major rows already).
// ---------------------------------------------------------------------------
__global__ __launch_bounds__(256) void k_gemm_nn(
    const float* __restrict__ A, const float* __restrict__ Bm, float* __restrict__ Cd,
    int M, int Nd, int K, size_t sA, size_t sB, size_t sC)
{
    __shared__ float As[16][68];
    __shared__ float Bs[16][68];
    int bz = blockIdx.z;
    int m0 = blockIdx.y * 64;
    int n0 = blockIdx.x * 64;
    const float* Ab  = A  + (size_t)bz * sA;
    const float* Bmb = Bm + (size_t)bz * sB;

    int t  = threadIdx.x;
    int tx = t & 15, ty = t >> 4;
    int amr = t >> 2, akc = (t & 3) * 4;    // A transpose-load
    int bkr = t >> 4, bnc = (t & 15) * 4;   // B direct load

    float acc[4][4] = {};
    for (int k0 = 0; k0 < K; k0 += 16) {
        int gm = m0 + amr;
        const float* ap = Ab + (size_t)gm * K + k0 + akc;
        #pragma unroll
        for (int i = 0; i < 4; i++)
            As[akc + i][amr] = (gm < M) ? ap[i] : 0.0f;
        const float* bp = Bmb + (size_t)(k0 + bkr) * Nd + n0 + bnc;
        #pragma unroll
        for (int i = 0; i < 4; i++)
            Bs[bkr][bnc + i] = (n0 + bnc + i < Nd) ? bp[i] : 0.0f;
        __syncthreads();
        #pragma unroll
        for (int kk = 0; kk < 16; kk++) {
            float4 a4 = *(const float4*)&As[kk][ty * 4];
            float4 b4 = *(const float4*)&Bs[kk][tx * 4];
            float av[4] = {a4.x, a4.y, a4.z, a4.w};
            float bv[4] = {b4.x, b4.y, b4.z, b4.w};
            #pragma unroll
            for (int i = 0; i < 4; i++)
                #pragma unroll
                for (int j = 0; j < 4; j++)
                    acc[i][j] += av[i] * bv[j];
        }
        __syncthreads();
    }
    #pragma unroll
    for (int i = 0; i < 4; i++) {
        int m = m0 + ty * 4 + i;
        if (m >= M) continue;
        #pragma unroll
        for (int j = 0; j < 4; j++) {
            int n = n0 + tx * 4 + j;
            if (n < Nd)
                Cd[(size_t)bz * sC + (size_t)m * Nd + n] = acc[i][j];
        }
    }
}

// ---------------------------------------------------------------------------
// Spatial softmax with gaussian prior: per row (b,p) of g_F (length Nn=288):
//   p1 = softmax(row); w = p1 * dis[p,:]; row = softmax(w)
// One block (288 threads) per row. grid = (Nn, Bb)
// ---------------------------------------------------------------------------
__global__ __launch_bounds__(288) void k_softmax_prior(const float* __restrict__ dis)
{
    int p = blockIdx.x;
    int b = blockIdx.y;
    float* f = g_F + ((size_t)b * Nn + p) * Nn;
    const float* d = dis + (size_t)p * Nn;
    int t = threadIdx.x;

    float v = f[t];
    float m1 = block_reduce(v, 0);
    float e1 = __expf(v - m1);
    float s1 = block_reduce(e1, 1);
    float w  = (e1 / s1) * d[t];
    float m2 = block_reduce(w, 0);
    float e2 = __expf(w - m2);
    float s2 = block_reduce(e2, 1);
    f[t] = e2 / s2;
}

// ---------------------------------------------------------------------------
// Channel softmax: rows of g_F2 (length Cc=1024), 256 threads x 4 elems.
// grid = Bb*Cc (1D)
// ---------------------------------------------------------------------------
__global__ __launch_bounds__(256) void k_softmax_chan()
{
    size_t row = blockIdx.x;
    float* f = g_F2 + row * (size_t)Cc;
    int t = threadIdx.x;

    float v[4];
    #pragma unroll
    for (int i = 0; i < 4; i++) v[i] = f[t + 256 * i];
    float lm = fmaxf(fmaxf(v[0], v[1]), fmaxf(v[2], v[3]));
    float m = block_reduce(lm, 0);
    float e[4], ls = 0.0f;
    #pragma unroll
    for (int i = 0; i < 4; i++) { e[i] = __expf(v[i] - m); ls += e[i]; }
    float s = block_reduce(ls, 1);
    float inv = 1.0f / s;
    #pragma unroll
    for (int i = 0; i < 4; i++) f[t + 256 * i] = e[i] * inv;
}

// ---------------------------------------------------------------------------
// BatchNorm stats: per channel mean/var over (B, N). Writes fused scale/shift.
// One block (256 thr) per channel.
// ---------------------------------------------------------------------------
__global__ __launch_bounds__(256) void k_bnstats(
    const float* __restrict__ Y,
    const float* __restrict__ gamma, const float* __restrict__ beta)
{
    int c = blockIdx.x;
    int t = threadIdx.x;
    float s = 0.0f, sq = 0.0f;
    for (int b = 0; b < Bb; b++) {
        const float* y = Y + ((size_t)b * Cc + c) * Nn;
        for (int i = t; i < Nn; i += 256) {
            float v = y[i];
            s  += v;
            sq += v * v;
        }
    }
    s  = block_reduce(s, 1);
    sq = block_reduce(sq, 1);
    if (t == 0) {
        const float invN = 1.0f / (float)(Bb * Nn);
        float mean = s * invN;
        float var  = sq * invN - mean * mean;
        float sc = gamma[c] * rsqrtf(var + EPSv);
        g_scale[c] = sc;
        g_shift[c] = beta[c] - mean * sc;
    }
}

// ---------------------------------------------------------------------------
// out = scale[c]*y + shift[c] + residual   (vectorized float4; Nn % 4 == 0)
// ---------------------------------------------------------------------------
__global__ __launch_bounds__(256) void k_bn_apply_add(
    const float* __restrict__ Y, const float* __restrict__ R, float* __restrict__ out)
{
    size_t i4 = (size_t)blockIdx.x * blockDim.x + threadIdx.x;
    const size_t total4 = (size_t)Bb * Cc * Nn / 4;
    if (i4 >= total4) return;
    size_t e = i4 * 4;
    int c = (int)((e / Nn) % Cc);
    float4 y = ((const float4*)Y)[i4];
    float4 r = ((const float4*)R)[i4];
    float sc = g_scale[c], sh = g_shift[c];
    float4 o;
    o.x = fmaf(sc, y.x, sh) + r.x;
    o.y = fmaf(sc, y.y, sh) + r.y;
    o.z = fmaf(sc, y.z, sh) + r.z;
    o.w = fmaf(sc, y.w, sh) + r.w;
    ((float4*)out)[i4] = o;
}

// ---------------------------------------------------------------------------
// Launch
// ---------------------------------------------------------------------------
extern "C" void kernel_launch(void* const* d_in, const int* in_sizes, int n_in,
                              void* d_out, int out_size)
{
    const float* x      = (const float*)d_in[0];
    const float* dis    = (const float*)d_in[1];
    const float* gamma1 = (const float*)d_in[2];
    const float* beta1  = (const float*)d_in[3];
    const float* gamma2 = (const float*)d_in[4];
    const float* beta2  = (const float*)d_in[5];
    float* out = (float*)d_out;

    float *pF, *pY, *pZ, *pY2, *pF2;
    cudaGetSymbolAddress((void**)&pF,  g_F);
    cudaGetSymbolAddress((void**)&pY,  g_Y);
    cudaGetSymbolAddress((void**)&pZ,  g_Z);
    cudaGetSymbolAddress((void**)&pY2, g_Y2);
    cudaGetSymbolAddress((void**)&pF2, g_F2);

    const size_t sXN = (size_t)Cc * Nn;   // per-batch stride of (C,N) tensors
    const size_t sFF = (size_t)Nn * Nn;   // per-batch stride of F
    const size_t sCC = (size_t)Cc * Cc;   // per-batch stride of F2

    // 1) F = X^T X / sqrt(C)          (288x288, K=1024)
    k_gemm_tn<<<dim3(5, 5, Bb), 256>>>(x, pF, Nn, Cc, Nn, sXN, sFF, 0.03125f);

    // 2) softmax -> *dis -> softmax   (in place on g_F)
    k_softmax_prior<<<dim3(Nn, Bb), 288>>>(dis);

    // 3) Y = X F^T                    (1024x288, K=288)
    k_gemm_nt<<<dim3(5, 16, Bb), 256>>>(x, pF, pY, Cc, Nn, Nn, sXN, sFF, sXN);

    // 4) BN1 stats + 5) Z = bn1(Y) + X
    k_bnstats<<<Cc, 256>>>(pY, gamma1, beta1);
    {
        size_t total4 = (size_t)Bb * Cc * Nn / 4;
        int blocks = (int)((total4 + 255) / 256);
        k_bn_apply_add<<<blocks, 256>>>(pY, x, pZ);
    }

    // 6) F2 = Z Z^T                   (1024x1024, K=288)
    k_gemm_nt<<<dim3(16, 16, Bb), 256>>>(pZ, pZ, pF2, Cc, Cc, Nn, sXN, sXN, sCC);

    // 7) softmax rows of F2
    k_softmax_chan<<<Bb * Cc, 256>>>();

    // 8) Y2 = F2 Z                    (1024x288, K=1024)
    k_gemm_nn<<<dim3(5, 16, Bb), 256>>>(pF2, pZ, pY2, Cc, Nn, Cc, sCC, sXN, sXN);

    // 9) BN2 stats + 10) out = bn2(Y2) + Z
    k_bnstats<<<Cc, 256>>>(pY2, gamma2, beta2);
    {
        size_t total4 = (size_t)Bb * Cc * Nn / 4;
        int blocks = (int)((total4 + 255) / 256);
        k_bn_apply_add<<<blocks, 256>>>(pY2, pZ, out);
    }
}

// round 3
// speedup vs baseline: 1.7315x; 1.7289x over previous
#include <cuda_runtime.h>
#include <math.h>

// Problem constants
#define Bb   128
#define Cc   1024
#define Hh   24
#define Ww   12
#define Nn   288           // H*W
#define EPSv 1e-5f

// ---------------------------------------------------------------------------
// Scratch (static device globals — allocation-free per harness rules)
// ---------------------------------------------------------------------------
__device__ float g_F [(size_t)Bb * Nn * Nn];   // spatial attention (b, n, n)
__device__ float g_Y [(size_t)Bb * Cc * Nn];   // spatial AV output
__device__ float g_Z [(size_t)Bb * Cc * Nn];   // residual 1 output
__device__ float g_Y2[(size_t)Bb * Cc * Nn];   // channel AV output
__device__ float g_F2[(size_t)Bb * Cc * Cc];   // channel attention (b, c, c)
__device__ float g_scale[Cc];
__device__ float g_shift[Cc];

// ---------------------------------------------------------------------------
// f32x2 packed helpers (FFMA2 — PTX only, ptxas never auto-emits)
// ---------------------------------------------------------------------------
__device__ __forceinline__ unsigned long long pack2(float x, float y) {
    unsigned long long r;
    asm("mov.b64 %0, {%1, %2};" : "=l"(r) : "f"(x), "f"(y));
    return r;
}
__device__ __forceinline__ float2 unpack2(unsigned long long v) {
    float2 r;
    asm("mov.b64 {%0, %1}, %2;" : "=f"(r.x), "=f"(r.y) : "l"(v));
    return r;
}
__device__ __forceinline__ void fma2(unsigned long long& d,
                                     unsigned long long a, unsigned long long b) {
    asm("fma.rn.f32x2 %0, %1, %2, %0;" : "+l"(d) : "l"(a), "l"(b));
}

// ---------------------------------------------------------------------------
// Block reduction helper (works for blockDim.x in {256, 288})
// op: 0 = max, 1 = sum
// ---------------------------------------------------------------------------
__device__ __forceinline__ float block_reduce(float v, int op) {
    __shared__ float red[32];
    #pragma unroll
    for (int o = 16; o > 0; o >>= 1) {
        float other = __shfl_xor_sync(0xffffffffu, v, o);
        v = op ? (v + other) : fmaxf(v, other);
    }
    int lane = threadIdx.x & 31;
    int wid  = threadIdx.x >> 5;
    int nw   = (blockDim.x + 31) >> 5;
    if (lane == 0) red[wid] = v;
    __syncthreads();
    if (wid == 0) {
        float r = (lane < nw) ? red[lane] : (op ? 0.0f : -3.4e38f);
        #pragma unroll
        for (int o = 16; o > 0; o >>= 1) {
            float other = __shfl_xor_sync(0xffffffffu, r, o);
            r = op ? (r + other) : fmaxf(r, other);
        }
        if (lane == 0) red[0] = r;
    }
    __syncthreads();
    float r = red[0];
    __syncthreads();
    return r;
}

// ---------------------------------------------------------------------------
// Unified f32x2 GEMM: C[b,m,n] = alpha * sum_k opA(A)[m,k] * opB(B)[k,n]
//   AT=false: A stored (K x M) row-major, row stride lda  (gram / NN-B style)
//   AT=true : A stored (M x K) row-major, row stride lda  (transpose-load)
//   BT=false: B stored (K x N) row-major, row stride ldb
//   BT=true : B stored (N x K) row-major, row stride ldb  (transpose-load)
// Tile 128(m) x 96(n) x 16(k), 256 threads, 8x6 microtile via FFMA2.
// Register-staged double buffering in smem.
// ---------------------------------------------------------------------------
template<bool AT, bool BT>
__global__ __launch_bounds__(256, 2) void k_gemm_f32x2(
    const float* __restrict__ A, const float* __restrict__ Bm, float* __restrict__ Cd,
    int M, int Nd, int K, int lda, int ldb,
    size_t sA, size_t sB, size_t sC, float alpha)
{
    __shared__ __align__(16) float As[2][16][128];
    __shared__ __align__(16) float Bs[2][16][98];

    const int bz = blockIdx.z;
    const int m0 = blockIdx.y * 128;
    const int n0 = blockIdx.x * 96;
    const float* Ab = A  + (size_t)bz * sA;
    const float* Bb_ = Bm + (size_t)bz * sB;

    const int t  = threadIdx.x;
    const int tx = t & 15;     // n group (6 cols each)
    const int ty = t >> 4;     // m group (8 rows each)

    // staging registers
    float rA[8];
    float rB[8];   // BT uses 8, direct uses 6

    // ---- global -> regs loader ----
    auto ldg_tile = [&](int k0) {
        if (AT) {
            int row = t >> 1, kc = (t & 1) * 8;
            bool v = (m0 + row) < M;
            const float* p = Ab + (size_t)(m0 + row) * lda + k0 + kc;
            float4 x0 = v ? *(const float4*)p       : make_float4(0,0,0,0);
            float4 x1 = v ? *(const float4*)(p + 4) : make_float4(0,0,0,0);
            rA[0]=x0.x; rA[1]=x0.y; rA[2]=x0.z; rA[3]=x0.w;
            rA[4]=x1.x; rA[5]=x1.y; rA[6]=x1.z; rA[7]=x1.w;
        } else {
            int k = t >> 4, mc = (t & 15) * 8;
            bool v = (m0 + mc) < M;           // M % 8 == 0 -> whole chunk validity
            const float* p = Ab + (size_t)(k0 + k) * lda + m0 + mc;
            float4 x0 = v ? *(const float4*)p       : make_float4(0,0,0,0);
            float4 x1 = v ? *(const float4*)(p + 4) : make_float4(0,0,0,0);
            rA[0]=x0.x; rA[1]=x0.y; rA[2]=x0.z; rA[3]=x0.w;
            rA[4]=x1.x; rA[5]=x1.y; rA[6]=x1.z; rA[7]=x1.w;
        }
        if (BT) {
            #pragma unroll
            for (int u = 0; u < 2; u++) {
                int idx = t + u * 256;          // 0..511 -> 384 used
                int row = idx >> 2, kc = (idx & 3) * 4;
                bool v = (row < 96) && ((n0 + row) < Nd);
                const float* p = Bb_ + (size_t)(n0 + row) * ldb + k0 + kc;
                float4 x = v ? *(const float4*)p : make_float4(0,0,0,0);
                rB[u*4+0]=x.x; rB[u*4+1]=x.y; rB[u*4+2]=x.z; rB[u*4+3]=x.w;
            }
        } else {
            int k = t >> 4, nc = (t & 15) * 6;
            const float* p = Bb_ + (size_t)(k0 + k) * ldb + n0 + nc;
            #pragma unroll
            for (int i = 0; i < 3; i++) {
                bool v = (n0 + nc + 2*i) < Nd;  // Nd even -> pair validity
                float2 x = v ? *(const float2*)(p + 2*i) : make_float2(0,0);
                rB[2*i]=x.x; rB[2*i+1]=x.y;
            }
        }
    };

    // ---- regs -> smem ----
    auto sts_tile = [&](int buf) {
        if (AT) {
            int row = t >> 1, kc = (t & 1) * 8;
            #pragma unroll
            for (int i = 0; i < 8; i++) As[buf][kc + i][row] = rA[i];
        } else {
            int k = t >> 4, mc = (t & 15) * 8;
            *(float4*)&As[buf][k][mc]     = make_float4(rA[0],rA[1],rA[2],rA[3]);
            *(float4*)&As[buf][k][mc + 4] = make_float4(rA[4],rA[5],rA[6],rA[7]);
        }
        if (BT) {
            #pragma unroll
            for (int u = 0; u < 2; u++) {
                int idx = t + u * 256;
                int row = idx >> 2, kc = (idx & 3) * 4;
                if (row < 96) {
                    #pragma unroll
                    for (int i = 0; i < 4; i++) Bs[buf][kc + i][row] = rB[u*4+i];
                }
            }
        } else {
            int k = t >> 4, nc = (t & 15) * 6;
            #pragma unroll
            for (int i = 0; i < 3; i++)
                *(float2*)&Bs[buf][k][nc + 2*i] = make_float2(rB[2*i], rB[2*i+1]);
        }
    };

    unsigned long long acc[8][3];
    #pragma unroll
    for (int i = 0; i < 8; i++)
        #pragma unroll
        for (int j = 0; j < 3; j++) acc[i][j] = 0ull;   // {+0.f, +0.f}

    const int nk = K / 16;
    ldg_tile(0);
    sts_tile(0);
    int p = 0;

    for (int kt = 0; kt < nk; kt++) {
        __syncthreads();
        if (kt + 1 < nk) ldg_tile((kt + 1) * 16);   // issue LDGs early

        #pragma unroll
        for (int kk = 0; kk < 16; kk++) {
            const float* ar = &As[p][kk][ty * 8];
            float4 a0 = *(const float4*)ar;
            float4 a1 = *(const float4*)(ar + 4);
            float av[8] = {a0.x,a0.y,a0.z,a0.w,a1.x,a1.y,a1.z,a1.w};
            const float* br = &Bs[p][kk][tx * 6];
            unsigned long long b0 = *(const unsigned long long*)br;
            unsigned long long b1 = *(const unsigned long long*)(br + 2);
            unsigned long long b2 = *(const unsigned long long*)(br + 4);
            #pragma unroll
            for (int i = 0; i < 8; i++) {
                unsigned long long ad = pack2(av[i], av[i]);
                fma2(acc[i][0], ad, b0);
                fma2(acc[i][1], ad, b1);
                fma2(acc[i][2], ad, b2);
            }
        }
        __syncthreads();
        if (kt + 1 < nk) sts_tile(p ^ 1);
        p ^= 1;
    }

    // epilogue
    #pragma unroll
    for (int i = 0; i < 8; i++) {
        int m = m0 + ty * 8 + i;
        if (m >= M) continue;
        float* cp = Cd + (size_t)bz * sC + (size_t)m * Nd + n0 + tx * 6;
        #pragma unroll
        for (int j = 0; j < 3; j++) {
            int n = n0 + tx * 6 + 2 * j;
            if (n < Nd) {
                float2 v = unpack2(acc[i][j]);
                v.x *= alpha; v.y *= alpha;
                *(float2*)(cp + 2 * j) = v;
            }
        }
    }
}

// ---------------------------------------------------------------------------
// Spatial softmax with gaussian prior: per row (b,p) of g_F (length Nn=288):
//   p1 = softmax(row); w = p1 * dis[p,:]; row = softmax(w)
// ---------------------------------------------------------------------------
__global__ __launch_bounds__(288) void k_softmax_prior(const float* __restrict__ dis)
{
    int p = blockIdx.x;
    int b = blockIdx.y;
    float* f = g_F + ((size_t)b * Nn + p) * Nn;
    const float* d = dis + (size_t)p * Nn;
    int t = threadIdx.x;

    float v = f[t];
    float m1 = block_reduce(v, 0);
    float e1 = __expf(v - m1);
    float s1 = block_reduce(e1, 1);
    float w  = (e1 / s1) * d[t];
    float m2 = block_reduce(w, 0);
    float e2 = __expf(w - m2);
    float s2 = block_reduce(e2, 1);
    f[t] = e2 / s2;
}

// ---------------------------------------------------------------------------
// Channel softmax: rows of g_F2 (length Cc=1024), 256 threads x 4 elems.
// ---------------------------------------------------------------------------
__global__ __launch_bounds__(256) void k_softmax_chan()
{
    size_t row = blockIdx.x;
    float* f = g_F2 + row * (size_t)Cc;
    int t = threadIdx.x;

    float v[4];
    #pragma unroll
    for (int i = 0; i < 4; i++) v[i] = f[t + 256 * i];
    float lm = fmaxf(fmaxf(v[0], v[1]), fmaxf(v[2], v[3]));
    float m = block_reduce(lm, 0);
    float e[4], ls = 0.0f;
    #pragma unroll
    for (int i = 0; i < 4; i++) { e[i] = __expf(v[i] - m); ls += e[i]; }
    float s = block_reduce(ls, 1);
    float inv = 1.0f / s;
    #pragma unroll
    for (int i = 0; i < 4; i++) f[t + 256 * i] = e[i] * inv;
}

// ---------------------------------------------------------------------------
// BatchNorm stats: per channel mean/var over (B, N). float4 + flat indexing.
// ---------------------------------------------------------------------------
__global__ __launch_bounds__(256) void k_bnstats(
    const float* __restrict__ Y,
    const float* __restrict__ gamma, const float* __restrict__ beta)
{
    int c = blockIdx.x;
    int t = threadIdx.x;
    const int n4 = Nn / 4;                 // 72
    const int tot4 = Bb * n4;              // 9216
    float s = 0.0f, sq = 0.0f;
    #pragma unroll 4
    for (int idx = t; idx < tot4; idx += 256) {
        int b = idx / n4;
        int i = idx - b * n4;
        float4 v = *(const float4*)(Y + ((size_t)b * Cc + c) * Nn + i * 4);
        s  += (v.x + v.y) + (v.z + v.w);
        sq += (v.x*v.x + v.y*v.y) + (v.z*v.z + v.w*v.w);
    }
    s  = block_reduce(s, 1);
    sq = block_reduce(sq, 1);
    if (t == 0) {
        const float invN = 1.0f / (float)(Bb * Nn);
        float mean = s * invN;
        float var  = sq * invN - mean * mean;
        float sc = gamma[c] * rsqrtf(var + EPSv);
        g_scale[c] = sc;
        g_shift[c] = beta[c] - mean * sc;
    }
}

// ---------------------------------------------------------------------------
// out = scale[c]*y + shift[c] + residual   (float4)
// ---------------------------------------------------------------------------
__global__ __launch_bounds__(256) void k_bn_apply_add(
    const float* __restrict__ Y, const float* __restrict__ R, float* __restrict__ out)
{
    size_t i4 = (size_t)blockIdx.x * blockDim.x + threadIdx.x;
    const size_t total4 = (size_t)Bb * Cc * Nn / 4;
    if (i4 >= total4) return;
    size_t e = i4 * 4;
    int c = (int)((e / Nn) % Cc);
    float4 y = ((const float4*)Y)[i4];
    float4 r = ((const float4*)R)[i4];
    float sc = g_scale[c], sh = g_shift[c];
    float4 o;
    o.x = fmaf(sc, y.x, sh) + r.x;
    o.y = fmaf(sc, y.y, sh) + r.y;
    o.z = fmaf(sc, y.z, sh) + r.z;
    o.w = fmaf(sc, y.w, sh) + r.w;
    ((float4*)out)[i4] = o;
}

// ---------------------------------------------------------------------------
// Launch
// ---------------------------------------------------------------------------
extern "C" void kernel_launch(void* const* d_in, const int* in_sizes, int n_in,
                              void* d_out, int out_size)
{
    const float* x      = (const float*)d_in[0];
    const float* dis    = (const float*)d_in[1];
    const float* gamma1 = (const float*)d_in[2];
    const float* beta1  = (const float*)d_in[3];
    const float* gamma2 = (const float*)d_in[4];
    const float* beta2  = (const float*)d_in[5];
    float* out = (float*)d_out;

    float *pF, *pY, *pZ, *pY2, *pF2;
    cudaGetSymbolAddress((void**)&pF,  g_F);
    cudaGetSymbolAddress((void**)&pY,  g_Y);
    cudaGetSymbolAddress((void**)&pZ,  g_Z);
    cudaGetSymbolAddress((void**)&pY2, g_Y2);
    cudaGetSymbolAddress((void**)&pF2, g_F2);

    const size_t sXN = (size_t)Cc * Nn;   // per-batch stride of (C,N) tensors
    const size_t sFF = (size_t)Nn * Nn;   // per-batch stride of F
    const size_t sCC = (size_t)Cc * Cc;   // per-batch stride of F2

    // 1) F = X^T X / sqrt(C)          M=N=288, K=1024 ; both operands K-major
    k_gemm_f32x2<false,false><<<dim3(3, 3, Bb), 256>>>(
        x, x, pF, Nn, Nn, Cc, Nn, Nn, sXN, sXN, sFF, 0.03125f);

    // 2) softmax -> *dis -> softmax   (in place on g_F)
    k_softmax_prior<<<dim3(Nn, Bb), 288>>>(dis);

    // 3) Y = X F^T                    M=1024, N=288, K=288 (NT)
    k_gemm_f32x2<true,true><<<dim3(3, 8, Bb), 256>>>(
        x, pF, pY, Cc, Nn, Nn, Nn, Nn, sXN, sFF, sXN, 1.0f);

    // 4) BN1 stats + 5) Z = bn1(Y) + X
    k_bnstats<<<Cc, 256>>>(pY, gamma1, beta1);
    {
        size_t total4 = (size_t)Bb * Cc * Nn / 4;
        int blocks = (int)((total4 + 255) / 256);
        k_bn_apply_add<<<blocks, 256>>>(pY, x, pZ);
    }

    // 6) F2 = Z Z^T                   M=N=1024, K=288 (NT)
    k_gemm_f32x2<true,true><<<dim3(11, 8, Bb), 256>>>(
        pZ, pZ, pF2, Cc, Cc, Nn, Nn, Nn, sXN, sXN, sCC, 1.0f);

    // 7) softmax rows of F2
    k_softmax_chan<<<Bb * Cc, 256>>>();

    // 8) Y2 = F2 Z                    M=1024, N=288, K=1024 (NN)
    k_gemm_f32x2<true,false><<<dim3(3, 8, Bb), 256>>>(
        pF2, pZ, pY2, Cc, Nn, Cc, Cc, Nn, sCC, sXN, sXN, 1.0f);

    // 9) BN2 stats + 10) out = bn2(Y2) + Z
    k_bnstats<<<Cc, 256>>>(pY2, gamma2, beta2);
    {
        size_t total4 = (size_t)Bb * Cc * Nn / 4;
        int blocks = (int)((total4 + 255) / 256);
        k_bn_apply_add<<<blocks, 256>>>(pY2, pZ, out);
    }
}